// round 11
// baseline (speedup 1.0000x reference)
#include <cuda_runtime.h>
#include <cstdint>

#define NN 4096
#define DD 1024
#define BM 256
#define BN 128
#define BK 32
#define NKT (DD / BK)                 // 32 k-tiles
#define TILE_F 4096                   // floats per 128x32 packed tile (16KB)
#define TILE_B 16384                  // bytes per packed tile
#define STAGE_B (3 * TILE_B)          // 48 KB per stage (2 A-tiles + 1 B-tile)
#define NSTAGE 4
#define GEMM_SMEM (NSTAGE * STAGE_B)  // 196608 B
#define NTHR 512

// Scratch (allocation-free: __device__ globals). Operands fragment-packed
// (tile-blocked [rowTile(128)][kTile(32)][4096]).
__device__ float g_xm[NN * DD];    // XM, A-packed for GEMM2   16 MB
__device__ float g_mt[DD * DD];    // M^T, B-packed for GEMM1   4 MB
__device__ float g_xlr[NN * DD];   // x_l, A-packed for GEMM1  16 MB
__device__ float g_xrr[NN * DD];   // x_r, B-packed for GEMM2  16 MB
__device__ float g_linl[NN];
__device__ float g_linr[NN];

__device__ __forceinline__ float tf32r(float x) {
    uint32_t y;
    asm("cvt.rna.tf32.f32 %0, %1;" : "=r"(y) : "f"(x));
    return __uint_as_float(y);
}
__device__ __forceinline__ uint32_t smaddr(const void* p) {
    uint64_t t;
    asm("cvta.to.shared.u64 %0, %1;" : "=l"(t) : "l"(p));
    return (uint32_t)t;
}
__device__ __forceinline__ void mbar_wait(uint32_t mbar, uint32_t parity) {
    asm volatile(
        "{\n\t.reg .pred P;\n\t"
        "WL_%=:\n\t"
        "mbarrier.try_wait.parity.acquire.cta.shared::cta.b64 P, [%0], %1, 0x989680;\n\t"
        "@P bra.uni WD_%=;\n\t"
        "bra.uni WL_%=;\n\t"
        "WD_%=:\n\t}"
        :: "r"(mbar), "r"(parity) : "memory");
}
__device__ __forceinline__ void bulk_cp(uint32_t dst, const void* src,
                                        uint32_t bytes, uint32_t mbar) {
    asm volatile(
        "cp.async.bulk.shared::cluster.global.mbarrier::complete_tx::bytes "
        "[%0], [%1], %2, [%3];"
        :: "r"(dst), "l"(src), "r"(bytes), "r"(mbar) : "memory");
}

// fragment-packed index of element (row, k) inside a 128x32 tile.
__device__ __forceinline__ int apack_inner(int row, int k) {
    int wm = row >> 5, mm = (row >> 4) & 1, sub8 = (row >> 3) & 1, g = row & 7;
    int kstep = k >> 3, half = (k >> 2) & 1, q = k & 3;
    return (((((kstep * 4 + wm) * 2 + mm) * 8 + g) * 4 + q) << 2) + half * 2 + sub8;
}
__device__ __forceinline__ int bpack_inner(int row, int k) {
    int wn = row >> 6, np = (row >> 4) & 3, nlo = (row >> 3) & 1, g = row & 7;
    int kstep = k >> 3, half = (k >> 2) & 1, q = k & 3;
    return (((((kstep * 2 + wn) * 4 + np) * 8 + g) * 4 + q) << 2) + nlo * 2 + half;
}

// ---------------------------------------------------------------------------
// lin terms: warp per row, float4 + shfl (exact fp32).
// ---------------------------------------------------------------------------
__global__ __launch_bounds__(256) void lin_kernel(
    const float* __restrict__ xl, const float* __restrict__ xr,
    const float* __restrict__ wl, const float* __restrict__ bl,
    const float* __restrict__ wr, const float* __restrict__ br)
{
    int gw   = (blockIdx.x * 256 + threadIdx.x) >> 5;
    int lane = threadIdx.x & 31;
    int right = gw >= NN;
    int row = right ? gw - NN : gw;
    const float* x = right ? xr : xl;
    const float* w = right ? wr : wl;
    const float4* xv = (const float4*)(x + (size_t)row * DD);
    const float4* wv = (const float4*)w;
    float s = 0.f;
    #pragma unroll
    for (int i = 0; i < 8; i++) {
        float4 a = xv[lane + i * 32];
        float4 b = wv[lane + i * 32];
        s += a.x * b.x + a.y * b.y + a.z * b.z + a.w * b.w;
    }
    #pragma unroll
    for (int o = 16; o; o >>= 1) s += __shfl_xor_sync(0xffffffffu, s, o);
    if (lane == 0) {
        if (right) g_linr[row] = s + br[0];
        else       g_linl[row] = s + bl[0];
    }
}

// ---------------------------------------------------------------------------
// Pack x (row-major [rows,1024]) into A- or B-packed tiles, tf32-rounded.
// ---------------------------------------------------------------------------
template <int APACK>
__global__ __launch_bounds__(256) void pack_kernel(
    const float* __restrict__ src, float* __restrict__ dst)
{
    int t = threadIdx.x;
    int r = t >> 1;
    int kOff = (t & 1) * 16;
    size_t srcBase = (size_t)(blockIdx.x * 128 + r) * DD + blockIdx.y * 32 + kOff;
    float* dTile = dst + ((size_t)blockIdx.x * NKT + blockIdx.y) * TILE_F;
    #pragma unroll
    for (int j = 0; j < 4; j++) {
        float4 v = *(const float4*)&src[srcBase + j * 4];
        int kl = kOff + j * 4;
        float vv[4] = {v.x, v.y, v.z, v.w};
        #pragma unroll
        for (int e = 0; e < 4; e++) {
            int idx = APACK ? apack_inner(r, kl + e) : bpack_inner(r, kl + e);
            dTile[idx] = tf32r(vv[e]);
        }
    }
}

// ---------------------------------------------------------------------------
// Pack M transposed into B-packed: g_mt[n][k] = M[k][n].
// ---------------------------------------------------------------------------
__global__ __launch_bounds__(256) void packT_kernel(
    const float* __restrict__ M, float* __restrict__ dst)
{
    int t = threadIdx.x;
    int k = t >> 3;
    int nOff = (t & 7) * 16;
    size_t srcBase = (size_t)(blockIdx.y * 32 + k) * DD + blockIdx.x * 128 + nOff;
    float* dTile = dst + ((size_t)blockIdx.x * NKT + blockIdx.y) * TILE_F;
    #pragma unroll
    for (int j = 0; j < 4; j++) {
        float4 v = *(const float4*)&M[srcBase + j * 4];
        int nl = nOff + j * 4;
        float vv[4] = {v.x, v.y, v.z, v.w};
        #pragma unroll
        for (int e = 0; e < 4; e++)
            dTile[bpack_inner(nl + e, k)] = tf32r(vv[e]);
    }
}

// ---------------------------------------------------------------------------
// tf32 NT GEMM on fragment-packed operands. Block 256x128x32, 512 threads
// (16 warps: 8M x 2N), warp tile 32x64, mma m16n8k8.
// cp.async.bulk + mbarrier 4-stage warp-async pipeline.
// ---------------------------------------------------------------------------
__global__ __launch_bounds__(NTHR, 1) void gemm_tc(
    const float* __restrict__ Apk, const float* __restrict__ Bpk,
    float* __restrict__ out,
    const int* __restrict__ mask, const float* __restrict__ bias,
    int mode, int write_x_half)
{
    extern __shared__ __align__(128) float4 sm4[];
    __shared__ __align__(8) uint64_t s_full[NSTAGE];
    __shared__ __align__(8) uint64_t s_empty[NSTAGE];

    const int tid  = threadIdx.x;
    const int lane = tid & 31;
    const int wid  = tid >> 5;       // 0..15
    const int wn   = wid & 1;        // 0..1
    const int wmp  = wid >> 1;       // 0..7  (M position in 256 rows)
    const int h    = wmp >> 2;       // which 128-row A tile
    const int wm   = wmp & 3;        // warp M within the tile
    const int g    = lane >> 2;
    const int q    = lane & 3;
    const int bx   = blockIdx.x;
    const int by   = blockIdx.y;

    const uint32_t smB    = smaddr(sm4);
    const uint32_t fullB  = smaddr(&s_full[0]);
    const uint32_t emptyB = smaddr(&s_empty[0]);

    if (tid == 0) {
        #pragma unroll
        for (int s = 0; s < NSTAGE; s++) {
            asm volatile("mbarrier.init.shared.b64 [%0], 1;"
                         :: "r"(fullB + 8u * s) : "memory");
            asm volatile("mbarrier.init.shared.b64 [%0], 16;"
                         :: "r"(emptyB + 8u * s) : "memory");
        }
    }
    __syncthreads();

    const char* Ag0 = (const char*)Apk + (size_t)(by * 2 + 0) * NKT * TILE_B;
    const char* Ag1 = (const char*)Apk + (size_t)(by * 2 + 1) * NKT * TILE_B;
    const char* Bg  = (const char*)Bpk + (size_t)bx * NKT * TILE_B;

    auto issue = [&](int u) {
        int s2 = u % NSTAGE;
        uint32_t fb = fullB + 8u * s2;
        asm volatile("mbarrier.arrive.expect_tx.shared.b64 _, [%0], %1;"
                     :: "r"(fb), "r"((uint32_t)STAGE_B) : "memory");
        uint32_t d = smB + (uint32_t)s2 * STAGE_B;
        bulk_cp(d,              Ag0 + (size_t)u * TILE_B, TILE_B, fb);
        bulk_cp(d + TILE_B,     Ag1 + (size_t)u * TILE_B, TILE_B, fb);
        bulk_cp(d + 2 * TILE_B, Bg  + (size_t)u * TILE_B, TILE_B, fb);
    };

    if (tid == 0) { issue(0); issue(1); issue(2); }

    float c[2][8][4];
    #pragma unroll
    for (int mm = 0; mm < 2; mm++)
        #pragma unroll
        for (int nn = 0; nn < 8; nn++)
            #pragma unroll
            for (int r = 0; r < 4; r++) c[mm][nn][r] = 0.f;

    for (int t = 0; t < NKT; t++) {
        int s = t % NSTAGE;
        if (tid == 0 && t + 3 < NKT) {
            int u = t + 3;
            if (u >= NSTAGE)
                mbar_wait(emptyB + 8u * (u % NSTAGE), (u / NSTAGE - 1) & 1);
            issue(u);
        }
        mbar_wait(fullB + 8u * s, (t / NSTAGE) & 1);

        const float4* Af = sm4 + s * (STAGE_B / 16) + h * (TILE_B / 16);
        const float4* Bf = sm4 + s * (STAGE_B / 16) + 2 * (TILE_B / 16);

        #pragma unroll
        for (int ks = 0; ks < 4; ks++) {
            float4 b4[4];
            #pragma unroll
            for (int np = 0; np < 4; np++)
                b4[np] = Bf[((ks * 2 + wn) * 4 + np) * 32 + lane];
            float4 a0 = Af[((ks * 4 + wm) * 2 + 0) * 32 + lane];
            float4 a1 = Af[((ks * 4 + wm) * 2 + 1) * 32 + lane];

            #pragma unroll
            for (int np = 0; np < 4; np++) {
                #pragma unroll
                for (int o = 0; o < 2; o++) {
                    int nn = np * 2 + o;
                    float bb0 = o ? b4[np].z : b4[np].x;
                    float bb1 = o ? b4[np].w : b4[np].y;
                    asm volatile(
                        "mma.sync.aligned.m16n8k8.row.col.f32.tf32.tf32.f32 "
                        "{%0,%1,%2,%3}, {%4,%5,%6,%7}, {%8,%9}, {%0,%1,%2,%3};"
                        : "+f"(c[0][nn][0]), "+f"(c[0][nn][1]),
                          "+f"(c[0][nn][2]), "+f"(c[0][nn][3])
                        : "r"(__float_as_uint(a0.x)), "r"(__float_as_uint(a0.y)),
                          "r"(__float_as_uint(a0.z)), "r"(__float_as_uint(a0.w)),
                          "r"(__float_as_uint(bb0)), "r"(__float_as_uint(bb1)));
                    asm volatile(
                        "mma.sync.aligned.m16n8k8.row.col.f32.tf32.tf32.f32 "
                        "{%0,%1,%2,%3}, {%4,%5,%6,%7}, {%8,%9}, {%0,%1,%2,%3};"
                        : "+f"(c[1][nn][0]), "+f"(c[1][nn][1]),
                          "+f"(c[1][nn][2]), "+f"(c[1][nn][3])
                        : "r"(__float_as_uint(a1.x)), "r"(__float_as_uint(a1.y)),
                          "r"(__float_as_uint(a1.z)), "r"(__float_as_uint(a1.w)),
                          "r"(__float_as_uint(bb0)), "r"(__float_as_uint(bb1)));
                }
            }
        }
        if (lane == 0)
            asm volatile("mbarrier.arrive.shared.b64 _, [%0];"
                         :: "r"(emptyB + 8u * s) : "memory");
    }

    if (mode == 0) {
        // store A-packed tf32 for GEMM2
        #pragma unroll
        for (int mm = 0; mm < 2; mm++) {
            int rowL = wmp * 32 + mm * 16 + g;           // 0..255
            size_t rowTB = (size_t)(by * 2 + (rowL >> 7)) * NKT;
            int rin = rowL & 127;
            #pragma unroll
            for (int nn = 0; nn < 8; nn++) {
                int colL = wn * 64 + nn * 8 + q * 2;     // 0..127
                size_t tb = (rowTB + bx * 4 + (colL >> 5)) * TILE_F;
                int kl = colL & 31;
                out[tb + apack_inner(rin,     kl)]     = tf32r(c[mm][nn][0]);
                out[tb + apack_inner(rin,     kl + 1)] = tf32r(c[mm][nn][1]);
                out[tb + apack_inner(rin + 8, kl)]     = tf32r(c[mm][nn][2]);
                out[tb + apack_inner(rin + 8, kl + 1)] = tf32r(c[mm][nn][3]);
            }
        }
    } else {
        const float b0v = bias[0];
        const size_t xoff = (size_t)NN * NN;
        const int rowBase = by * BM;
        const int colBase = bx * BN;
        #pragma unroll
        for (int mm = 0; mm < 2; mm++) {
            int row0 = rowBase + wmp * 32 + mm * 16 + g;
            int row1 = row0 + 8;
            float ll0 = g_linl[row0] + b0v;
            float ll1 = g_linl[row1] + b0v;
            #pragma unroll
            for (int nn = 0; nn < 8; nn++) {
                int col = colBase + wn * 64 + nn * 8 + q * 2;
                float lr0 = g_linr[col];
                float lr1 = g_linr[col + 1];
                float v00 = c[mm][nn][0] + ll0 + lr0; v00 = v00 > 0.f ? v00 : 0.f;
                float v01 = c[mm][nn][1] + ll0 + lr1; v01 = v01 > 0.f ? v01 : 0.f;
                float v10 = c[mm][nn][2] + ll1 + lr0; v10 = v10 > 0.f ? v10 : 0.f;
                float v11 = c[mm][nn][3] + ll1 + lr1; v11 = v11 > 0.f ? v11 : 0.f;
                size_t b0i = (size_t)row0 * NN + col;
                size_t b1i = (size_t)row1 * NN + col;
                if (write_x_half) {
                    *(float2*)&out[xoff + b0i] = make_float2(v00, v01);
                    *(float2*)&out[xoff + b1i] = make_float2(v10, v11);
                }
                int2 m0 = *(const int2*)&mask[b0i];
                int2 m1 = *(const int2*)&mask[b1i];
                *(float2*)&out[b0i] = make_float2(m0.x ? v00 : 0.f, m0.y ? v01 : 0.f);
                *(float2*)&out[b1i] = make_float2(m1.x ? v10 : 0.f, m1.y ? v11 : 0.f);
            }
        }
    }
}

// ---------------------------------------------------------------------------
extern "C" void kernel_launch(void* const* d_in, const int* in_sizes, int n_in,
                              void* d_out, int out_size)
{
    const float* xl     = (const float*)d_in[0];
    const float* xr     = (const float*)d_in[1];
    const int*   mask   = (const int*)d_in[2];
    const float* matrix = (const float*)d_in[3];
    const float* bias   = (const float*)d_in[4];
    const float* wl     = (const float*)d_in[5];
    const float* bl     = (const float*)d_in[6];
    const float* wr     = (const float*)d_in[7];
    const float* br     = (const float*)d_in[8];
    float* out = (float*)d_out;

    int write_x_half = (out_size >= 2 * NN * NN) ? 1 : 0;

    cudaFuncSetAttribute(gemm_tc,
                         cudaFuncAttributeMaxDynamicSharedMemorySize, GEMM_SMEM);

    float *xm, *mt, *xlr, *xrr;
    cudaGetSymbolAddress((void**)&xm, g_xm);
    cudaGetSymbolAddress((void**)&mt, g_mt);
    cudaGetSymbolAddress((void**)&xlr, g_xlr);
    cudaGetSymbolAddress((void**)&xrr, g_xrr);

    // 1) prep: lin terms (exact), packed tf32 operands
    lin_kernel<<<1024, 256>>>(xl, xr, wl, bl, wr, br);
    pack_kernel<1><<<dim3(NN / 128, NKT), 256>>>(xl, xlr);   // A-packed x_l
    pack_kernel<0><<<dim3(NN / 128, NKT), 256>>>(xr, xrr);   // B-packed x_r
    packT_kernel<<<dim3(DD / 128, NKT), 256>>>(matrix, mt);  // B-packed M^T

    // 2) XM = tf32(x_l) @ M -> A-packed g_xm
    gemm_tc<<<dim3(DD / BN, NN / BM), NTHR, GEMM_SMEM>>>(
        xlr, mt, xm, nullptr, nullptr, 0, 0);

    // 3) S = XM @ tf32(x_r)^T + epilogue
    gemm_tc<<<dim3(NN / BN, NN / BM), NTHR, GEMM_SMEM>>>(
        xm, xrr, out, mask, bias, 1, write_x_half);
}

// round 13
// speedup vs baseline: 1.0286x; 1.0286x over previous
#include <cuda_runtime.h>
#include <cstdint>

#define NN 4096
#define DD 1024
#define BM 128
#define BN 128
#define BK 32
#define NKT (DD / BK)                 // 32 k-tiles per output tile
#define TILE_F 4096                   // floats per 128x32 packed tile (16KB)
#define TILE_B 16384                  // bytes per packed tile
#define STAGE_B (2 * TILE_B)          // 32 KB per stage (A + B)
#define NSTAGE 3
#define GEMM_SMEM (NSTAGE * STAGE_B)  // 98304 B
#define NCTA 296                      // 2 CTAs/SM x 148 SMs, persistent

// Scratch (allocation-free: __device__ globals). Operands fragment-packed
// (tile-blocked [rowTile(128)][kTile(32)][4096]).
__device__ float g_xm[NN * DD];    // XM, A-packed for GEMM2   16 MB
__device__ float g_mt[DD * DD];    // M^T, B-packed for GEMM1   4 MB
__device__ float g_xlr[NN * DD];   // x_l, A-packed for GEMM1  16 MB
__device__ float g_xrr[NN * DD];   // x_r, B-packed for GEMM2  16 MB
__device__ float g_linl[NN];
__device__ float g_linr[NN];

__device__ __forceinline__ float tf32r(float x) {
    uint32_t y;
    asm("cvt.rna.tf32.f32 %0, %1;" : "=r"(y) : "f"(x));
    return __uint_as_float(y);
}
__device__ __forceinline__ uint32_t smaddr(const void* p) {
    uint64_t t;
    asm("cvta.to.shared.u64 %0, %1;" : "=l"(t) : "l"(p));
    return (uint32_t)t;
}
__device__ __forceinline__ void mbar_wait(uint32_t mbar, uint32_t parity) {
    asm volatile(
        "{\n\t.reg .pred P;\n\t"
        "WL_%=:\n\t"
        "mbarrier.try_wait.parity.acquire.cta.shared::cta.b64 P, [%0], %1, 0x989680;\n\t"
        "@P bra.uni WD_%=;\n\t"
        "bra.uni WL_%=;\n\t"
        "WD_%=:\n\t}"
        :: "r"(mbar), "r"(parity) : "memory");
}
__device__ __forceinline__ void bulk_cp(uint32_t dst, const void* src,
                                        uint32_t bytes, uint32_t mbar) {
    asm volatile(
        "cp.async.bulk.shared::cluster.global.mbarrier::complete_tx::bytes "
        "[%0], [%1], %2, [%3];"
        :: "r"(dst), "l"(src), "r"(bytes), "r"(mbar) : "memory");
}

// fragment-packed index of element (row, k) inside a 128x32 tile.
__device__ __forceinline__ int apack_inner(int row, int k) {
    int wm = row >> 5, mm = (row >> 4) & 1, sub8 = (row >> 3) & 1, g = row & 7;
    int kstep = k >> 3, half = (k >> 2) & 1, q = k & 3;
    return (((((kstep * 4 + wm) * 2 + mm) * 8 + g) * 4 + q) << 2) + half * 2 + sub8;
}
__device__ __forceinline__ int bpack_inner(int row, int k) {
    int wn = row >> 6, np = (row >> 4) & 3, nlo = (row >> 3) & 1, g = row & 7;
    int kstep = k >> 3, half = (k >> 2) & 1, q = k & 3;
    return (((((kstep * 2 + wn) * 4 + np) * 8 + g) * 4 + q) << 2) + nlo * 2 + half;
}

// ---------------------------------------------------------------------------
// lin terms: warp per row, float4 + shfl (exact fp32).
// ---------------------------------------------------------------------------
__global__ __launch_bounds__(256) void lin_kernel(
    const float* __restrict__ xl, const float* __restrict__ xr,
    const float* __restrict__ wl, const float* __restrict__ bl,
    const float* __restrict__ wr, const float* __restrict__ br)
{
    int gw   = (blockIdx.x * 256 + threadIdx.x) >> 5;
    int lane = threadIdx.x & 31;
    int right = gw >= NN;
    int row = right ? gw - NN : gw;
    const float* x = right ? xr : xl;
    const float* w = right ? wr : wl;
    const float4* xv = (const float4*)(x + (size_t)row * DD);
    const float4* wv = (const float4*)w;
    float s = 0.f;
    #pragma unroll
    for (int i = 0; i < 8; i++) {
        float4 a = xv[lane + i * 32];
        float4 b = wv[lane + i * 32];
        s += a.x * b.x + a.y * b.y + a.z * b.z + a.w * b.w;
    }
    #pragma unroll
    for (int o = 16; o; o >>= 1) s += __shfl_xor_sync(0xffffffffu, s, o);
    if (lane == 0) {
        if (right) g_linr[row] = s + br[0];
        else       g_linl[row] = s + bl[0];
    }
}

// ---------------------------------------------------------------------------
// Pack x (row-major [rows,1024]) into A- or B-packed tiles, tf32-rounded.
// ---------------------------------------------------------------------------
template <int APACK>
__global__ __launch_bounds__(256) void pack_kernel(
    const float* __restrict__ src, float* __restrict__ dst)
{
    int t = threadIdx.x;
    int r = t >> 1;
    int kOff = (t & 1) * 16;
    size_t srcBase = (size_t)(blockIdx.x * 128 + r) * DD + blockIdx.y * 32 + kOff;
    float* dTile = dst + ((size_t)blockIdx.x * NKT + blockIdx.y) * TILE_F;
    #pragma unroll
    for (int j = 0; j < 4; j++) {
        float4 v = *(const float4*)&src[srcBase + j * 4];
        int kl = kOff + j * 4;
        float vv[4] = {v.x, v.y, v.z, v.w};
        #pragma unroll
        for (int e = 0; e < 4; e++) {
            int idx = APACK ? apack_inner(r, kl + e) : bpack_inner(r, kl + e);
            dTile[idx] = tf32r(vv[e]);
        }
    }
}

// ---------------------------------------------------------------------------
// Pack M transposed into B-packed: g_mt[n][k] = M[k][n].
// ---------------------------------------------------------------------------
__global__ __launch_bounds__(256) void packT_kernel(
    const float* __restrict__ M, float* __restrict__ dst)
{
    int t = threadIdx.x;
    int k = t >> 3;
    int nOff = (t & 7) * 16;
    size_t srcBase = (size_t)(blockIdx.y * 32 + k) * DD + blockIdx.x * 128 + nOff;
    float* dTile = dst + ((size_t)blockIdx.x * NKT + blockIdx.y) * TILE_F;
    #pragma unroll
    for (int j = 0; j < 4; j++) {
        float4 v = *(const float4*)&M[srcBase + j * 4];
        int nl = nOff + j * 4;
        float vv[4] = {v.x, v.y, v.z, v.w};
        #pragma unroll
        for (int e = 0; e < 4; e++)
            dTile[bpack_inner(nl + e, k)] = tf32r(vv[e]);
    }
}

// ---------------------------------------------------------------------------
// Persistent tf32 NT GEMM on fragment-packed operands.
// 296 CTAs loop over output tiles; ONE continuous 3-stage bulk+mbarrier
// pipeline spans tile boundaries. Prefetch distance = 2 (ring depth - 1).
// Block tile 128x128x32, 8 warps (4Mx2N), mma m16n8k8.
// ---------------------------------------------------------------------------
__global__ __launch_bounds__(256, 2) void gemm_tc(
    const float* __restrict__ Apk, const float* __restrict__ Bpk,
    float* __restrict__ out,
    const int* __restrict__ mask, const float* __restrict__ bias,
    int nt, int nx, int mode, int write_x_half)
{
    extern __shared__ __align__(128) float4 sm4[];
    __shared__ __align__(8) uint64_t s_full[NSTAGE];
    __shared__ __align__(8) uint64_t s_empty[NSTAGE];

    const int tid  = threadIdx.x;
    const int lane = tid & 31;
    const int wid  = tid >> 5;
    const int wm   = wid >> 1;
    const int wn   = wid & 1;
    const int g    = lane >> 2;
    const int q    = lane & 3;
    const int bid  = blockIdx.x;

    const uint32_t smB    = smaddr(sm4);
    const uint32_t fullB  = smaddr(&s_full[0]);
    const uint32_t emptyB = smaddr(&s_empty[0]);

    if (tid == 0) {
        #pragma unroll
        for (int s = 0; s < NSTAGE; s++) {
            asm volatile("mbarrier.init.shared.b64 [%0], 1;"
                         :: "r"(fullB + 8u * s) : "memory");
            asm volatile("mbarrier.init.shared.b64 [%0], 8;"
                         :: "r"(emptyB + 8u * s) : "memory");
        }
    }
    __syncthreads();

    // load index j -> (output tile, k-tile); issues A+B bulk copies
    auto issue = [&](int j) {
        int it2 = bid + (j >> 5) * NCTA;
        if (it2 >= nt) return;
        int k   = j & 31;
        int bx2 = it2 % nx;
        int by2 = it2 / nx;
        int s2  = j % NSTAGE;
        uint32_t fb = fullB + 8u * s2;
        asm volatile("mbarrier.arrive.expect_tx.shared.b64 _, [%0], %1;"
                     :: "r"(fb), "r"((uint32_t)STAGE_B) : "memory");
        uint32_t d = smB + (uint32_t)s2 * STAGE_B;
        bulk_cp(d,          (const char*)Apk + ((size_t)by2 * NKT + k) * TILE_B,
                TILE_B, fb);
        bulk_cp(d + TILE_B, (const char*)Bpk + ((size_t)bx2 * NKT + k) * TILE_B,
                TILE_B, fb);
    };

    if (tid == 0) { issue(0); issue(1); }

    int Tg = 0;  // global k-tile compute counter (continuous pipeline position)

    for (int it = bid; it < nt; it += NCTA) {
        const int bx = it % nx;
        const int by = it / nx;

        float c[2][8][4];
        #pragma unroll
        for (int mm = 0; mm < 2; mm++)
            #pragma unroll
            for (int nn = 0; nn < 8; nn++)
                #pragma unroll
                for (int r = 0; r < 4; r++) c[mm][nn][r] = 0.f;

        for (int k = 0; k < NKT; k++, Tg++) {
            int s = Tg % NSTAGE;
            if (tid == 0) {
                int j = Tg + 2;                      // prefetch distance 2
                int it2 = bid + (j >> 5) * NCTA;
                if (it2 < nt) {
                    if (j >= NSTAGE)
                        mbar_wait(emptyB + 8u * (j % NSTAGE),
                                  (j / NSTAGE - 1) & 1);
                    issue(j);
                }
            }
            mbar_wait(fullB + 8u * s, (Tg / NSTAGE) & 1);

            const float4* Af = sm4 + s * (STAGE_B / 16);
            const float4* Bf = Af + (TILE_B / 16);

            #pragma unroll
            for (int ks = 0; ks < 4; ks++) {
                float4 b4[4];
                #pragma unroll
                for (int np = 0; np < 4; np++)
                    b4[np] = Bf[((ks * 2 + wn) * 4 + np) * 32 + lane];
                float4 a0 = Af[((ks * 4 + wm) * 2 + 0) * 32 + lane];
                float4 a1 = Af[((ks * 4 + wm) * 2 + 1) * 32 + lane];

                #pragma unroll
                for (int np = 0; np < 4; np++) {
                    #pragma unroll
                    for (int o = 0; o < 2; o++) {
                        int nn = np * 2 + o;
                        float bb0 = o ? b4[np].z : b4[np].x;
                        float bb1 = o ? b4[np].w : b4[np].y;
                        asm volatile(
                            "mma.sync.aligned.m16n8k8.row.col.f32.tf32.tf32.f32 "
                            "{%0,%1,%2,%3}, {%4,%5,%6,%7}, {%8,%9}, {%0,%1,%2,%3};"
                            : "+f"(c[0][nn][0]), "+f"(c[0][nn][1]),
                              "+f"(c[0][nn][2]), "+f"(c[0][nn][3])
                            : "r"(__float_as_uint(a0.x)), "r"(__float_as_uint(a0.y)),
                              "r"(__float_as_uint(a0.z)), "r"(__float_as_uint(a0.w)),
                              "r"(__float_as_uint(bb0)), "r"(__float_as_uint(bb1)));
                        asm volatile(
                            "mma.sync.aligned.m16n8k8.row.col.f32.tf32.tf32.f32 "
                            "{%0,%1,%2,%3}, {%4,%5,%6,%7}, {%8,%9}, {%0,%1,%2,%3};"
                            : "+f"(c[1][nn][0]), "+f"(c[1][nn][1]),
                              "+f"(c[1][nn][2]), "+f"(c[1][nn][3])
                            : "r"(__float_as_uint(a1.x)), "r"(__float_as_uint(a1.y)),
                              "r"(__float_as_uint(a1.z)), "r"(__float_as_uint(a1.w)),
                              "r"(__float_as_uint(bb0)), "r"(__float_as_uint(bb1)));
                    }
                }
            }
            if (lane == 0)
                asm volatile("mbarrier.arrive.shared.b64 _, [%0];"
                             :: "r"(emptyB + 8u * s) : "memory");
        }

        if (mode == 0) {
            #pragma unroll
            for (int mm = 0; mm < 2; mm++) {
                #pragma unroll
                for (int nn = 0; nn < 8; nn++) {
                    int colL = wn * 64 + nn * 8 + q * 2;
                    int rowL = wm * 32 + mm * 16 + g;
                    size_t tb = ((size_t)by * NKT + bx * 4 + (colL >> 5)) * TILE_F;
                    int kl = colL & 31;
                    out[tb + apack_inner(rowL,     kl)]     = tf32r(c[mm][nn][0]);
                    out[tb + apack_inner(rowL,     kl + 1)] = tf32r(c[mm][nn][1]);
                    out[tb + apack_inner(rowL + 8, kl)]     = tf32r(c[mm][nn][2]);
                    out[tb + apack_inner(rowL + 8, kl + 1)] = tf32r(c[mm][nn][3]);
                }
            }
        } else {
            const float b0v = bias[0];
            const size_t xoff = (size_t)NN * NN;
            const int rowBase = by * BM;
            const int colBase = bx * BN;
            #pragma unroll
            for (int mm = 0; mm < 2; mm++) {
                int row0 = rowBase + wm * 32 + mm * 16 + g;
                int row1 = row0 + 8;
                float ll0 = g_linl[row0] + b0v;
                float ll1 = g_linl[row1] + b0v;
                #pragma unroll
                for (int nn = 0; nn < 8; nn++) {
                    int col = colBase + wn * 64 + nn * 8 + q * 2;
                    float lr0 = g_linr[col];
                    float lr1 = g_linr[col + 1];
                    float v00 = c[mm][nn][0] + ll0 + lr0; v00 = v00 > 0.f ? v00 : 0.f;
                    float v01 = c[mm][nn][1] + ll0 + lr1; v01 = v01 > 0.f ? v01 : 0.f;
                    float v10 = c[mm][nn][2] + ll1 + lr0; v10 = v10 > 0.f ? v10 : 0.f;
                    float v11 = c[mm][nn][3] + ll1 + lr1; v11 = v11 > 0.f ? v11 : 0.f;
                    size_t b0i = (size_t)row0 * NN + col;
                    size_t b1i = (size_t)row1 * NN + col;
                    if (write_x_half) {
                        *(float2*)&out[xoff + b0i] = make_float2(v00, v01);
                        *(float2*)&out[xoff + b1i] = make_float2(v10, v11);
                    }
                    int2 m0 = *(const int2*)&mask[b0i];
                    int2 m1 = *(const int2*)&mask[b1i];
                    *(float2*)&out[b0i] = make_float2(m0.x ? v00 : 0.f, m0.y ? v01 : 0.f);
                    *(float2*)&out[b1i] = make_float2(m1.x ? v10 : 0.f, m1.y ? v11 : 0.f);
                }
            }
        }
    }
}

// ---------------------------------------------------------------------------
extern "C" void kernel_launch(void* const* d_in, const int* in_sizes, int n_in,
                              void* d_out, int out_size)
{
    const float* xl     = (const float*)d_in[0];
    const float* xr     = (const float*)d_in[1];
    const int*   mask   = (const int*)d_in[2];
    const float* matrix = (const float*)d_in[3];
    const float* bias   = (const float*)d_in[4];
    const float* wl     = (const float*)d_in[5];
    const float* bl     = (const float*)d_in[6];
    const float* wr     = (const float*)d_in[7];
    const float* br     = (const float*)d_in[8];
    float* out = (float*)d_out;

    int write_x_half = (out_size >= 2 * NN * NN) ? 1 : 0;

    cudaFuncSetAttribute(gemm_tc,
                         cudaFuncAttributeMaxDynamicSharedMemorySize, GEMM_SMEM);

    float *xm, *mt, *xlr, *xrr;
    cudaGetSymbolAddress((void**)&xm, g_xm);
    cudaGetSymbolAddress((void**)&mt, g_mt);
    cudaGetSymbolAddress((void**)&xlr, g_xlr);
    cudaGetSymbolAddress((void**)&xrr, g_xrr);

    // 1) prep: lin terms (exact), packed tf32 operands
    lin_kernel<<<1024, 256>>>(xl, xr, wl, bl, wr, br);
    pack_kernel<1><<<dim3(NN / 128, NKT), 256>>>(xl, xlr);   // A-packed x_l
    pack_kernel<0><<<dim3(NN / 128, NKT), 256>>>(xr, xrr);   // B-packed x_r
    packT_kernel<<<dim3(DD / 128, NKT), 256>>>(matrix, mt);  // B-packed M^T

    // 2) XM = tf32(x_l) @ M -> A-packed g_xm   (256 tiles, 8 per row)
    gemm_tc<<<NCTA, 256, GEMM_SMEM>>>(
        xlr, mt, xm, nullptr, nullptr, (NN / BM) * (DD / BN), DD / BN, 0, 0);

    // 3) S = XM @ tf32(x_r)^T + epilogue        (1024 tiles, 32 per row)
    gemm_tc<<<NCTA, 256, GEMM_SMEM>>>(
        xm, xrr, out, mask, bias, (NN / BM) * (NN / BN), NN / BN, 1, write_x_half);
}

// round 15
// speedup vs baseline: 1.2412x; 1.2068x over previous
#include <cuda_runtime.h>
#include <cstdint>

#define NN 4096
#define DD 1024
#define BM 128
#define BN 128
#define BK 32
#define NKT (DD / BK)                 // 32 k-tiles
#define TILE_F 4096                   // floats per 128x32 packed tile (16KB)
#define TILE_B 16384                  // bytes per packed tile
#define STAGE_B (2 * TILE_B)          // 32 KB per stage (A + B)
#define NSTAGE 3
#define GEMM_SMEM (NSTAGE * STAGE_B)  // 98304 B

// Scratch (allocation-free: __device__ globals). Operands fragment-packed
// (tile-blocked [rowTile(128)][kTile(32)][4096]).
__device__ float g_xm[NN * DD];    // XM, A-packed for GEMM2   16 MB
__device__ float g_mt[DD * DD];    // M^T, B-packed for GEMM1   4 MB
__device__ float g_xlr[NN * DD];   // x_l, A-packed for GEMM1  16 MB
__device__ float g_xrr[NN * DD];   // x_r, B-packed for GEMM2  16 MB
__device__ float g_linl[NN];
__device__ float g_linr[NN];

__device__ __forceinline__ float tf32r(float x) {
    uint32_t y;
    asm("cvt.rna.tf32.f32 %0, %1;" : "=r"(y) : "f"(x));
    return __uint_as_float(y);
}
__device__ __forceinline__ uint32_t smaddr(const void* p) {
    uint64_t t;
    asm("cvta.to.shared.u64 %0, %1;" : "=l"(t) : "l"(p));
    return (uint32_t)t;
}
__device__ __forceinline__ void mbar_wait(uint32_t mbar, uint32_t parity) {
    asm volatile(
        "{\n\t.reg .pred P;\n\t"
        "WL_%=:\n\t"
        "mbarrier.try_wait.parity.acquire.cta.shared::cta.b64 P, [%0], %1, 0x989680;\n\t"
        "@P bra.uni WD_%=;\n\t"
        "bra.uni WL_%=;\n\t"
        "WD_%=:\n\t}"
        :: "r"(mbar), "r"(parity) : "memory");
}
__device__ __forceinline__ void bulk_cp(uint32_t dst, const void* src,
                                        uint32_t bytes, uint32_t mbar) {
    asm volatile(
        "cp.async.bulk.shared::cluster.global.mbarrier::complete_tx::bytes "
        "[%0], [%1], %2, [%3];"
        :: "r"(dst), "l"(src), "r"(bytes), "r"(mbar) : "memory");
}

// fragment-packed index of element (row, k) inside a 128x32 tile.
__device__ __forceinline__ int apack_inner(int row, int k) {
    int wm = row >> 5, mm = (row >> 4) & 1, sub8 = (row >> 3) & 1, g = row & 7;
    int kstep = k >> 3, half = (k >> 2) & 1, q = k & 3;
    return (((((kstep * 4 + wm) * 2 + mm) * 8 + g) * 4 + q) << 2) + half * 2 + sub8;
}
__device__ __forceinline__ int bpack_inner(int row, int k) {
    int wn = row >> 6, np = (row >> 4) & 3, nlo = (row >> 3) & 1, g = row & 7;
    int kstep = k >> 3, half = (k >> 2) & 1, q = k & 3;
    return (((((kstep * 2 + wn) * 4 + np) * 8 + g) * 4 + q) << 2) + nlo * 2 + half;
}

// ---------------------------------------------------------------------------
// Fused prep: one launch covering all independent prep jobs.
//   blocks [0,1024)     : pack x_l -> g_xlr (A-packed)
//   blocks [1024,2048)  : pack x_r -> g_xrr (B-packed)
//   blocks [2048,2304)  : pack M^T -> g_mt  (B-packed, transposed)
//   blocks [2304,3328)  : lin terms (warp per row)
// ---------------------------------------------------------------------------
__global__ __launch_bounds__(256) void prep_kernel(
    const float* __restrict__ xl, const float* __restrict__ xr,
    const float* __restrict__ matrix,
    const float* __restrict__ wl, const float* __restrict__ bl,
    const float* __restrict__ wr, const float* __restrict__ br)
{
    const int b = blockIdx.x;
    const int t = threadIdx.x;

    if (b < 2048) {
        // pack x_l (A-packed) or x_r (B-packed)
        int apack = (b < 1024);
        int bb = apack ? b : b - 1024;
        const float* src = apack ? xl : xr;
        float* dst = apack ? g_xlr : g_xrr;
        int rowTile = bb >> 5;
        int kTile   = bb & 31;
        int r    = t >> 1;
        int kOff = (t & 1) * 16;
        size_t srcBase = (size_t)(rowTile * 128 + r) * DD + kTile * 32 + kOff;
        float* dTile = dst + ((size_t)rowTile * NKT + kTile) * TILE_F;
        #pragma unroll
        for (int j = 0; j < 4; j++) {
            float4 v = *(const float4*)&src[srcBase + j * 4];
            int kl = kOff + j * 4;
            float vv[4] = {v.x, v.y, v.z, v.w};
            #pragma unroll
            for (int e = 0; e < 4; e++) {
                int idx = apack ? apack_inner(r, kl + e) : bpack_inner(r, kl + e);
                dTile[idx] = tf32r(vv[e]);
            }
        }
    } else if (b < 2304) {
        // pack M transposed: g_mt[n][k] = M[k][n]
        int bb = b - 2048;
        int nTile = bb >> 5;
        int kTile = bb & 31;
        int k    = t >> 3;
        int nOff = (t & 7) * 16;
        size_t srcBase = (size_t)(kTile * 32 + k) * DD + nTile * 128 + nOff;
        float* dTile = g_mt + ((size_t)nTile * NKT + kTile) * TILE_F;
        #pragma unroll
        for (int j = 0; j < 4; j++) {
            float4 v = *(const float4*)&matrix[srcBase + j * 4];
            int nl = nOff + j * 4;
            float vv[4] = {v.x, v.y, v.z, v.w};
            #pragma unroll
            for (int e = 0; e < 4; e++)
                dTile[bpack_inner(nl + e, k)] = tf32r(vv[e]);
        }
    } else {
        // lin terms: warp per row
        int gw   = ((b - 2304) * 256 + t) >> 5;
        int lane = t & 31;
        int right = gw >= NN;
        int row = right ? gw - NN : gw;
        const float* x = right ? xr : xl;
        const float* w = right ? wr : wl;
        const float4* xv = (const float4*)(x + (size_t)row * DD);
        const float4* wv = (const float4*)w;
        float s = 0.f;
        #pragma unroll
        for (int i = 0; i < 8; i++) {
            float4 a = xv[lane + i * 32];
            float4 bv = wv[lane + i * 32];
            s += a.x * bv.x + a.y * bv.y + a.z * bv.z + a.w * bv.w;
        }
        #pragma unroll
        for (int o = 16; o; o >>= 1) s += __shfl_xor_sync(0xffffffffu, s, o);
        if (lane == 0) {
            if (right) g_linr[row] = s + br[0];
            else       g_linl[row] = s + bl[0];
        }
    }
}

// ---------------------------------------------------------------------------
// tf32 NT GEMM on fragment-packed operands (R10 configuration).
// cp.async.bulk + mbarrier warp-asynchronous 3-stage pipeline (no syncthreads
// in the mainloop). Block 128x128x32, 8 warps (4Mx2N), mma m16n8k8.
// ---------------------------------------------------------------------------
__global__ __launch_bounds__(256, 2) void gemm_tc(
    const float* __restrict__ Apk, const float* __restrict__ Bpk,
    float* __restrict__ out,
    const int* __restrict__ mask, const float* __restrict__ bias,
    int mode, int write_x_half)
{
    extern __shared__ __align__(128) float4 sm4[];
    __shared__ __align__(8) uint64_t s_full[NSTAGE];
    __shared__ __align__(8) uint64_t s_empty[NSTAGE];

    const int tid  = threadIdx.x;
    const int lane = tid & 31;
    const int wid  = tid >> 5;
    const int wm   = wid >> 1;
    const int wn   = wid & 1;
    const int g    = lane >> 2;
    const int q    = lane & 3;
    const int bx   = blockIdx.x;
    const int by   = blockIdx.y;

    const uint32_t smB    = smaddr(sm4);
    const uint32_t fullB  = smaddr(&s_full[0]);
    const uint32_t emptyB = smaddr(&s_empty[0]);

    if (tid == 0) {
        #pragma unroll
        for (int s = 0; s < NSTAGE; s++) {
            asm volatile("mbarrier.init.shared.b64 [%0], 1;"
                         :: "r"(fullB + 8u * s) : "memory");
            asm volatile("mbarrier.init.shared.b64 [%0], 8;"
                         :: "r"(emptyB + 8u * s) : "memory");
        }
    }
    __syncthreads();

    const char* Ag = (const char*)Apk + (size_t)by * NKT * TILE_B;
    const char* Bg = (const char*)Bpk + (size_t)bx * NKT * TILE_B;

    auto issue = [&](int u) {
        int s2 = u % NSTAGE;
        uint32_t fb = fullB + 8u * s2;
        asm volatile("mbarrier.arrive.expect_tx.shared.b64 _, [%0], %1;"
                     :: "r"(fb), "r"((uint32_t)STAGE_B) : "memory");
        uint32_t d = smB + (uint32_t)s2 * STAGE_B;
        bulk_cp(d,          Ag + (size_t)u * TILE_B, TILE_B, fb);
        bulk_cp(d + TILE_B, Bg + (size_t)u * TILE_B, TILE_B, fb);
    };

    if (tid == 0) { issue(0); issue(1); }

    float c[2][8][4];
    #pragma unroll
    for (int mm = 0; mm < 2; mm++)
        #pragma unroll
        for (int nn = 0; nn < 8; nn++)
            #pragma unroll
            for (int r = 0; r < 4; r++) c[mm][nn][r] = 0.f;

    for (int t = 0; t < NKT; t++) {
        int s = t % NSTAGE;
        if (tid == 0 && t + 2 < NKT) {
            int u = t + 2;
            if (u >= NSTAGE)
                mbar_wait(emptyB + 8u * (u % NSTAGE), (u / NSTAGE - 1) & 1);
            issue(u);
        }
        mbar_wait(fullB + 8u * s, (t / NSTAGE) & 1);

        const float4* Af = sm4 + s * (STAGE_B / 16);
        const float4* Bf = Af + (TILE_B / 16);

        #pragma unroll
        for (int ks = 0; ks < 4; ks++) {
            float4 b4[4];
            #pragma unroll
            for (int np = 0; np < 4; np++)
                b4[np] = Bf[((ks * 2 + wn) * 4 + np) * 32 + lane];
            float4 a0 = Af[((ks * 4 + wm) * 2 + 0) * 32 + lane];
            float4 a1 = Af[((ks * 4 + wm) * 2 + 1) * 32 + lane];

            #pragma unroll
            for (int np = 0; np < 4; np++) {
                #pragma unroll
                for (int o = 0; o < 2; o++) {
                    int nn = np * 2 + o;
                    float bb0 = o ? b4[np].z : b4[np].x;
                    float bb1 = o ? b4[np].w : b4[np].y;
                    asm volatile(
                        "mma.sync.aligned.m16n8k8.row.col.f32.tf32.tf32.f32 "
                        "{%0,%1,%2,%3}, {%4,%5,%6,%7}, {%8,%9}, {%0,%1,%2,%3};"
                        : "+f"(c[0][nn][0]), "+f"(c[0][nn][1]),
                          "+f"(c[0][nn][2]), "+f"(c[0][nn][3])
                        : "r"(__float_as_uint(a0.x)), "r"(__float_as_uint(a0.y)),
                          "r"(__float_as_uint(a0.z)), "r"(__float_as_uint(a0.w)),
                          "r"(__float_as_uint(bb0)), "r"(__float_as_uint(bb1)));
                    asm volatile(
                        "mma.sync.aligned.m16n8k8.row.col.f32.tf32.tf32.f32 "
                        "{%0,%1,%2,%3}, {%4,%5,%6,%7}, {%8,%9}, {%0,%1,%2,%3};"
                        : "+f"(c[1][nn][0]), "+f"(c[1][nn][1]),
                          "+f"(c[1][nn][2]), "+f"(c[1][nn][3])
                        : "r"(__float_as_uint(a1.x)), "r"(__float_as_uint(a1.y)),
                          "r"(__float_as_uint(a1.z)), "r"(__float_as_uint(a1.w)),
                          "r"(__float_as_uint(bb0)), "r"(__float_as_uint(bb1)));
                }
            }
        }
        if (lane == 0)
            asm volatile("mbarrier.arrive.shared.b64 _, [%0];"
                         :: "r"(emptyB + 8u * s) : "memory");
    }

    if (mode == 0) {
        // store A-packed tf32 for GEMM2
        #pragma unroll
        for (int mm = 0; mm < 2; mm++) {
            #pragma unroll
            for (int nn = 0; nn < 8; nn++) {
                int colL = wn * 64 + nn * 8 + q * 2;
                int rowL = wm * 32 + mm * 16 + g;
                size_t tb = ((size_t)by * NKT + bx * 4 + (colL >> 5)) * TILE_F;
                int kl = colL & 31;
                out[tb + apack_inner(rowL,     kl)]     = tf32r(c[mm][nn][0]);
                out[tb + apack_inner(rowL,     kl + 1)] = tf32r(c[mm][nn][1]);
                out[tb + apack_inner(rowL + 8, kl)]     = tf32r(c[mm][nn][2]);
                out[tb + apack_inner(rowL + 8, kl + 1)] = tf32r(c[mm][nn][3]);
            }
        }
    } else {
        const float b0v = bias[0];
        const size_t xoff = (size_t)NN * NN;
        const int rowBase = by * BM;
        const int colBase = bx * BN;
        #pragma unroll
        for (int mm = 0; mm < 2; mm++) {
            int row0 = rowBase + wm * 32 + mm * 16 + g;
            int row1 = row0 + 8;
            float ll0 = g_linl[row0] + b0v;
            float ll1 = g_linl[row1] + b0v;
            #pragma unroll
            for (int nn = 0; nn < 8; nn++) {
                int col = colBase + wn * 64 + nn * 8 + q * 2;
                float lr0 = g_linr[col];
                float lr1 = g_linr[col + 1];
                float v00 = c[mm][nn][0] + ll0 + lr0; v00 = v00 > 0.f ? v00 : 0.f;
                float v01 = c[mm][nn][1] + ll0 + lr1; v01 = v01 > 0.f ? v01 : 0.f;
                float v10 = c[mm][nn][2] + ll1 + lr0; v10 = v10 > 0.f ? v10 : 0.f;
                float v11 = c[mm][nn][3] + ll1 + lr1; v11 = v11 > 0.f ? v11 : 0.f;
                size_t b0i = (size_t)row0 * NN + col;
                size_t b1i = (size_t)row1 * NN + col;
                if (write_x_half) {
                    *(float2*)&out[xoff + b0i] = make_float2(v00, v01);
                    *(float2*)&out[xoff + b1i] = make_float2(v10, v11);
                }
                int2 m0 = *(const int2*)&mask[b0i];
                int2 m1 = *(const int2*)&mask[b1i];
                *(float2*)&out[b0i] = make_float2(m0.x ? v00 : 0.f, m0.y ? v01 : 0.f);
                *(float2*)&out[b1i] = make_float2(m1.x ? v10 : 0.f, m1.y ? v11 : 0.f);
            }
        }
    }
}

// ---------------------------------------------------------------------------
extern "C" void kernel_launch(void* const* d_in, const int* in_sizes, int n_in,
                              void* d_out, int out_size)
{
    const float* xl     = (const float*)d_in[0];
    const float* xr     = (const float*)d_in[1];
    const int*   mask   = (const int*)d_in[2];
    const float* matrix = (const float*)d_in[3];
    const float* bias   = (const float*)d_in[4];
    const float* wl     = (const float*)d_in[5];
    const float* bl     = (const float*)d_in[6];
    const float* wr     = (const float*)d_in[7];
    const float* br     = (const float*)d_in[8];
    float* out = (float*)d_out;

    int write_x_half = (out_size >= 2 * NN * NN) ? 1 : 0;

    cudaFuncSetAttribute(gemm_tc,
                         cudaFuncAttributeMaxDynamicSharedMemorySize, GEMM_SMEM);

    float *xm, *mt, *xlr, *xrr;
    cudaGetSymbolAddress((void**)&xm, g_xm);
    cudaGetSymbolAddress((void**)&mt, g_mt);
    cudaGetSymbolAddress((void**)&xlr, g_xlr);
    cudaGetSymbolAddress((void**)&xrr, g_xrr);

    // 1) fused prep: packs + transpose-pack + lin terms in one launch
    prep_kernel<<<3328, 256>>>(xl, xr, matrix, wl, bl, wr, br);

    // 2) XM = tf32(x_l) @ M -> A-packed g_xm
    gemm_tc<<<dim3(DD / BN, NN / BM), 256, GEMM_SMEM>>>(
        xlr, mt, xm, nullptr, nullptr, 0, 0);

    // 3) S = XM @ tf32(x_r)^T + epilogue
    gemm_tc<<<dim3(NN / BN, NN / BM), 256, GEMM_SMEM>>>(
        xm, xrr, out, mask, bias, 1, write_x_half);
}

// round 16
// speedup vs baseline: 1.2749x; 1.0271x over previous
#include <cuda_runtime.h>
#include <cstdint>

#define NN 4096
#define DD 1024
#define BM 128
#define BN 128
#define BK 32
#define NKT (DD / BK)                 // 32 k-tiles
#define TILE_F 4096                   // floats per 128x32 packed tile (16KB)
#define TILE_B 16384                  // bytes per packed tile
#define STAGE_B (2 * TILE_B)          // 32 KB per stage (A + B)
#define NSTAGE 3
#define GEMM_SMEM (NSTAGE * STAGE_B)  // 98304 B

// Scratch (allocation-free: __device__ globals). Operands fragment-packed
// (tile-blocked [rowTile(128)][kTile(32)][4096]).
__device__ float g_xm[NN * DD];    // XM, A-packed for GEMM2   16 MB
__device__ float g_mt[DD * DD];    // M^T, B-packed for GEMM1   4 MB
__device__ float g_xlr[NN * DD];   // x_l, A-packed for GEMM1  16 MB
__device__ float g_xrr[NN * DD];   // x_r, B-packed for GEMM2  16 MB
__device__ float g_linl[NN];
__device__ float g_linr[NN];

__device__ __forceinline__ float tf32r(float x) {
    uint32_t y;
    asm("cvt.rna.tf32.f32 %0, %1;" : "=r"(y) : "f"(x));
    return __uint_as_float(y);
}
__device__ __forceinline__ uint32_t smaddr(const void* p) {
    uint64_t t;
    asm("cvta.to.shared.u64 %0, %1;" : "=l"(t) : "l"(p));
    return (uint32_t)t;
}
__device__ __forceinline__ void mbar_wait(uint32_t mbar, uint32_t parity) {
    asm volatile(
        "{\n\t.reg .pred P;\n\t"
        "WL_%=:\n\t"
        "mbarrier.try_wait.parity.acquire.cta.shared::cta.b64 P, [%0], %1, 0x989680;\n\t"
        "@P bra.uni WD_%=;\n\t"
        "bra.uni WL_%=;\n\t"
        "WD_%=:\n\t}"
        :: "r"(mbar), "r"(parity) : "memory");
}
__device__ __forceinline__ void bulk_cp(uint32_t dst, const void* src,
                                        uint32_t bytes, uint32_t mbar) {
    asm volatile(
        "cp.async.bulk.shared::cluster.global.mbarrier::complete_tx::bytes "
        "[%0], [%1], %2, [%3];"
        :: "r"(dst), "l"(src), "r"(bytes), "r"(mbar) : "memory");
}

// fragment-packed index of element (row, k) inside a 128x32 tile.
__device__ __forceinline__ int apack_inner(int row, int k) {
    int wm = row >> 5, mm = (row >> 4) & 1, sub8 = (row >> 3) & 1, g = row & 7;
    int kstep = k >> 3, half = (k >> 2) & 1, q = k & 3;
    return (((((kstep * 4 + wm) * 2 + mm) * 8 + g) * 4 + q) << 2) + half * 2 + sub8;
}
__device__ __forceinline__ int bpack_inner(int row, int k) {
    int wn = row >> 6, np = (row >> 4) & 3, nlo = (row >> 3) & 1, g = row & 7;
    int kstep = k >> 3, half = (k >> 2) & 1, q = k & 3;
    return (((((kstep * 2 + wn) * 4 + np) * 8 + g) * 4 + q) << 2) + nlo * 2 + half;
}

// ---------------------------------------------------------------------------
// Fused prep: one launch covering all independent prep jobs.
//   blocks [0,1024)     : pack x_l -> g_xlr (A-packed, vectorized)
//   blocks [1024,2048)  : pack x_r -> g_xrr (B-packed, vectorized)
//   blocks [2048,2304)  : pack M^T -> g_mt  (B-packed, transposed)
//   blocks [2304,3328)  : lin terms (warp per row)
// ---------------------------------------------------------------------------
__global__ __launch_bounds__(256) void prep_kernel(
    const float* __restrict__ xl, const float* __restrict__ xr,
    const float* __restrict__ matrix,
    const float* __restrict__ wl, const float* __restrict__ bl,
    const float* __restrict__ wr, const float* __restrict__ br)
{
    const int b = blockIdx.x;
    const int t = threadIdx.x;

    if (b < 2048) {
        // Vectorized x pack. Thread unit: one row pair (row, row+8) x one kstep.
        // Loads 2x2 float4, emits 4 contiguous STG.128.
        int apack = (b < 1024);
        int bb = apack ? b : b - 1024;
        const float* src = apack ? xl : xr;
        float* dst = apack ? g_xlr : g_xrr;
        int rowTile = bb >> 5;
        int kTile   = bb & 31;

        int p  = t & 63;           // row-pair index
        int ks = t >> 6;           // kstep 0..3
        int g2 = p & 7;
        int row = ((p >> 3) << 4) + g2;       // 0..127, bit3 == 0

        size_t sb = (size_t)(rowTile * 128 + row) * DD + kTile * 32 + ks * 8;
        float4 u0 = *(const float4*)&src[sb];
        float4 u1 = *(const float4*)&src[sb + 4];
        float4 v0 = *(const float4*)&src[sb + 8 * DD];
        float4 v1 = *(const float4*)&src[sb + 8 * DD + 4];
        float a0[8] = {tf32r(u0.x), tf32r(u0.y), tf32r(u0.z), tf32r(u0.w),
                       tf32r(u1.x), tf32r(u1.y), tf32r(u1.z), tf32r(u1.w)};
        float a8[8] = {tf32r(v0.x), tf32r(v0.y), tf32r(v0.z), tf32r(v0.w),
                       tf32r(v1.x), tf32r(v1.y), tf32r(v1.z), tf32r(v1.w)};

        float* dTile = dst + ((size_t)rowTile * NKT + kTile) * TILE_F;
        if (apack) {
            int wm = row >> 5, mm = (row >> 4) & 1;
            int base = ((((ks * 4 + wm) * 2 + mm) * 8 + g2) * 4) * 4;
            #pragma unroll
            for (int q = 0; q < 4; q++)
                *(float4*)&dTile[base + q * 4] =
                    make_float4(a0[q], a8[q], a0[q + 4], a8[q + 4]);
        } else {
            int wn = row >> 6, np = (row >> 4) & 3;
            int base = ((((ks * 2 + wn) * 4 + np) * 8 + g2) * 4) * 4;
            #pragma unroll
            for (int q = 0; q < 4; q++)
                *(float4*)&dTile[base + q * 4] =
                    make_float4(a0[q], a0[q + 4], a8[q], a8[q + 4]);
        }
    } else if (b < 2304) {
        // pack M transposed: g_mt[n][k] = M[k][n]  (unchanged; small)
        int bb = b - 2048;
        int nTile = bb >> 5;
        int kTile = bb & 31;
        int k    = t >> 3;
        int nOff = (t & 7) * 16;
        size_t srcBase = (size_t)(kTile * 32 + k) * DD + nTile * 128 + nOff;
        float* dTile = g_mt + ((size_t)nTile * NKT + kTile) * TILE_F;
        #pragma unroll
        for (int j = 0; j < 4; j++) {
            float4 v = *(const float4*)&matrix[srcBase + j * 4];
            int nl = nOff + j * 4;
            float vv[4] = {v.x, v.y, v.z, v.w};
            #pragma unroll
            for (int e = 0; e < 4; e++)
                dTile[bpack_inner(nl + e, k)] = tf32r(vv[e]);
        }
    } else {
        // lin terms: warp per row
        int gw   = ((b - 2304) * 256 + t) >> 5;
        int lane = t & 31;
        int right = gw >= NN;
        int row = right ? gw - NN : gw;
        const float* x = right ? xr : xl;
        const float* w = right ? wr : wl;
        const float4* xv = (const float4*)(x + (size_t)row * DD);
        const float4* wv = (const float4*)w;
        float s = 0.f;
        #pragma unroll
        for (int i = 0; i < 8; i++) {
            float4 a = xv[lane + i * 32];
            float4 bv = wv[lane + i * 32];
            s += a.x * bv.x + a.y * bv.y + a.z * bv.z + a.w * bv.w;
        }
        #pragma unroll
        for (int o = 16; o; o >>= 1) s += __shfl_xor_sync(0xffffffffu, s, o);
        if (lane == 0) {
            if (right) g_linr[row] = s + br[0];
            else       g_linl[row] = s + bl[0];
        }
    }
}

// ---------------------------------------------------------------------------
// tf32 NT GEMM on fragment-packed operands (R10 configuration).
// cp.async.bulk + mbarrier warp-asynchronous 3-stage pipeline (no syncthreads
// in the mainloop). Block 128x128x32, 8 warps (4Mx2N), mma m16n8k8.
// ---------------------------------------------------------------------------
__global__ __launch_bounds__(256, 2) void gemm_tc(
    const float* __restrict__ Apk, const float* __restrict__ Bpk,
    float* __restrict__ out,
    const int* __restrict__ mask, const float* __restrict__ bias,
    int mode, int write_x_half)
{
    extern __shared__ __align__(128) float4 sm4[];
    __shared__ __align__(8) uint64_t s_full[NSTAGE];
    __shared__ __align__(8) uint64_t s_empty[NSTAGE];

    const int tid  = threadIdx.x;
    const int lane = tid & 31;
    const int wid  = tid >> 5;
    const int wm   = wid >> 1;
    const int wn   = wid & 1;
    const int g    = lane >> 2;
    const int q    = lane & 3;
    const int bx   = blockIdx.x;
    const int by   = blockIdx.y;

    const uint32_t smB    = smaddr(sm4);
    const uint32_t fullB  = smaddr(&s_full[0]);
    const uint32_t emptyB = smaddr(&s_empty[0]);

    if (tid == 0) {
        #pragma unroll
        for (int s = 0; s < NSTAGE; s++) {
            asm volatile("mbarrier.init.shared.b64 [%0], 1;"
                         :: "r"(fullB + 8u * s) : "memory");
            asm volatile("mbarrier.init.shared.b64 [%0], 8;"
                         :: "r"(emptyB + 8u * s) : "memory");
        }
    }
    __syncthreads();

    const char* Ag = (const char*)Apk + (size_t)by * NKT * TILE_B;
    const char* Bg = (const char*)Bpk + (size_t)bx * NKT * TILE_B;

    auto issue = [&](int u) {
        int s2 = u % NSTAGE;
        uint32_t fb = fullB + 8u * s2;
        asm volatile("mbarrier.arrive.expect_tx.shared.b64 _, [%0], %1;"
                     :: "r"(fb), "r"((uint32_t)STAGE_B) : "memory");
        uint32_t d = smB + (uint32_t)s2 * STAGE_B;
        bulk_cp(d,          Ag + (size_t)u * TILE_B, TILE_B, fb);
        bulk_cp(d + TILE_B, Bg + (size_t)u * TILE_B, TILE_B, fb);
    };

    if (tid == 0) { issue(0); issue(1); }

    float c[2][8][4];
    #pragma unroll
    for (int mm = 0; mm < 2; mm++)
        #pragma unroll
        for (int nn = 0; nn < 8; nn++)
            #pragma unroll
            for (int r = 0; r < 4; r++) c[mm][nn][r] = 0.f;

    for (int t = 0; t < NKT; t++) {
        int s = t % NSTAGE;
        if (tid == 0 && t + 2 < NKT) {
            int u = t + 2;
            if (u >= NSTAGE)
                mbar_wait(emptyB + 8u * (u % NSTAGE), (u / NSTAGE - 1) & 1);
            issue(u);
        }
        mbar_wait(fullB + 8u * s, (t / NSTAGE) & 1);

        const float4* Af = sm4 + s * (STAGE_B / 16);
        const float4* Bf = Af + (TILE_B / 16);

        #pragma unroll
        for (int ks = 0; ks < 4; ks++) {
            float4 b4[4];
            #pragma unroll
            for (int np = 0; np < 4; np++)
                b4[np] = Bf[((ks * 2 + wn) * 4 + np) * 32 + lane];
            float4 a0 = Af[((ks * 4 + wm) * 2 + 0) * 32 + lane];
            float4 a1 = Af[((ks * 4 + wm) * 2 + 1) * 32 + lane];

            #pragma unroll
            for (int np = 0; np < 4; np++) {
                #pragma unroll
                for (int o = 0; o < 2; o++) {
                    int nn = np * 2 + o;
                    float bb0 = o ? b4[np].z : b4[np].x;
                    float bb1 = o ? b4[np].w : b4[np].y;
                    asm volatile(
                        "mma.sync.aligned.m16n8k8.row.col.f32.tf32.tf32.f32 "
                        "{%0,%1,%2,%3}, {%4,%5,%6,%7}, {%8,%9}, {%0,%1,%2,%3};"
                        : "+f"(c[0][nn][0]), "+f"(c[0][nn][1]),
                          "+f"(c[0][nn][2]), "+f"(c[0][nn][3])
                        : "r"(__float_as_uint(a0.x)), "r"(__float_as_uint(a0.y)),
                          "r"(__float_as_uint(a0.z)), "r"(__float_as_uint(a0.w)),
                          "r"(__float_as_uint(bb0)), "r"(__float_as_uint(bb1)));
                    asm volatile(
                        "mma.sync.aligned.m16n8k8.row.col.f32.tf32.tf32.f32 "
                        "{%0,%1,%2,%3}, {%4,%5,%6,%7}, {%8,%9}, {%0,%1,%2,%3};"
                        : "+f"(c[1][nn][0]), "+f"(c[1][nn][1]),
                          "+f"(c[1][nn][2]), "+f"(c[1][nn][3])
                        : "r"(__float_as_uint(a1.x)), "r"(__float_as_uint(a1.y)),
                          "r"(__float_as_uint(a1.z)), "r"(__float_as_uint(a1.w)),
                          "r"(__float_as_uint(bb0)), "r"(__float_as_uint(bb1)));
                }
            }
        }
        if (lane == 0)
            asm volatile("mbarrier.arrive.shared.b64 _, [%0];"
                         :: "r"(emptyB + 8u * s) : "memory");
    }

    if (mode == 0) {
        // store A-packed tf32 for GEMM2
        #pragma unroll
        for (int mm = 0; mm < 2; mm++) {
            #pragma unroll
            for (int nn = 0; nn < 8; nn++) {
                int colL = wn * 64 + nn * 8 + q * 2;
                int rowL = wm * 32 + mm * 16 + g;
                size_t tb = ((size_t)by * NKT + bx * 4 + (colL >> 5)) * TILE_F;
                int kl = colL & 31;
                out[tb + apack_inner(rowL,     kl)]     = tf32r(c[mm][nn][0]);
                out[tb + apack_inner(rowL,     kl + 1)] = tf32r(c[mm][nn][1]);
                out[tb + apack_inner(rowL + 8, kl)]     = tf32r(c[mm][nn][2]);
                out[tb + apack_inner(rowL + 8, kl + 1)] = tf32r(c[mm][nn][3]);
            }
        }
    } else {
        const float b0v = bias[0];
        const size_t xoff = (size_t)NN * NN;
        const int rowBase = by * BM;
        const int colBase = bx * BN;
        #pragma unroll
        for (int mm = 0; mm < 2; mm++) {
            int row0 = rowBase + wm * 32 + mm * 16 + g;
            int row1 = row0 + 8;
            float ll0 = g_linl[row0] + b0v;
            float ll1 = g_linl[row1] + b0v;
            #pragma unroll
            for (int nn = 0; nn < 8; nn++) {
                int col = colBase + wn * 64 + nn * 8 + q * 2;
                float lr0 = g_linr[col];
                float lr1 = g_linr[col + 1];
                float v00 = c[mm][nn][0] + ll0 + lr0; v00 = v00 > 0.f ? v00 : 0.f;
                float v01 = c[mm][nn][1] + ll0 + lr1; v01 = v01 > 0.f ? v01 : 0.f;
                float v10 = c[mm][nn][2] + ll1 + lr0; v10 = v10 > 0.f ? v10 : 0.f;
                float v11 = c[mm][nn][3] + ll1 + lr1; v11 = v11 > 0.f ? v11 : 0.f;
                size_t b0i = (size_t)row0 * NN + col;
                size_t b1i = (size_t)row1 * NN + col;
                if (write_x_half) {
                    *(float2*)&out[xoff + b0i] = make_float2(v00, v01);
                    *(float2*)&out[xoff + b1i] = make_float2(v10, v11);
                }
                int2 m0 = *(const int2*)&mask[b0i];
                int2 m1 = *(const int2*)&mask[b1i];
                *(float2*)&out[b0i] = make_float2(m0.x ? v00 : 0.f, m0.y ? v01 : 0.f);
                *(float2*)&out[b1i] = make_float2(m1.x ? v10 : 0.f, m1.y ? v11 : 0.f);
            }
        }
    }
}

// ---------------------------------------------------------------------------
extern "C" void kernel_launch(void* const* d_in, const int* in_sizes, int n_in,
                              void* d_out, int out_size)
{
    const float* xl     = (const float*)d_in[0];
    const float* xr     = (const float*)d_in[1];
    const int*   mask   = (const int*)d_in[2];
    const float* matrix = (const float*)d_in[3];
    const float* bias   = (const float*)d_in[4];
    const float* wl     = (const float*)d_in[5];
    const float* bl     = (const float*)d_in[6];
    const float* wr     = (const float*)d_in[7];
    const float* br     = (const float*)d_in[8];
    float* out = (float*)d_out;

    int write_x_half = (out_size >= 2 * NN * NN) ? 1 : 0;

    cudaFuncSetAttribute(gemm_tc,
                         cudaFuncAttributeMaxDynamicSharedMemorySize, GEMM_SMEM);

    float *xm, *mt, *xlr, *xrr;
    cudaGetSymbolAddress((void**)&xm, g_xm);
    cudaGetSymbolAddress((void**)&mt, g_mt);
    cudaGetSymbolAddress((void**)&xlr, g_xlr);
    cudaGetSymbolAddress((void**)&xrr, g_xrr);

    // 1) fused prep: packs + transpose-pack + lin terms in one launch
    prep_kernel<<<3328, 256>>>(xl, xr, matrix, wl, bl, wr, br);

    // 2) XM = tf32(x_l) @ M -> A-packed g_xm
    gemm_tc<<<dim3(DD / BN, NN / BM), 256, GEMM_SMEM>>>(
        xlr, mt, xm, nullptr, nullptr, 0, 0);

    // 3) S = XM @ tf32(x_r)^T + epilogue
    gemm_tc<<<dim3(NN / BN, NN / BM), 256, GEMM_SMEM>>>(
        xm, xrr, out, mask, bias, 1, write_x_half);
}

// round 17
// speedup vs baseline: 1.2980x; 1.0182x over previous
#include <cuda_runtime.h>
#include <cstdint>

#define NN 4096
#define DD 1024
#define BM 128
#define BN 128
#define BK 32
#define NKT (DD / BK)                 // 32 k-tiles
#define TILE_F 4096                   // floats per 128x32 packed tile (16KB)
#define TILE_B 16384                  // bytes per packed tile
#define STAGE_B (2 * TILE_B)          // 32 KB per stage (A + B)
#define NSTAGE 3
#define GEMM_SMEM (NSTAGE * STAGE_B)  // 98304 B

// Scratch (allocation-free: __device__ globals). Operands fragment-packed
// (tile-blocked [rowTile(128)][kTile(32)][4096]).
__device__ float g_xm[NN * DD];    // XM, A-packed for GEMM2   16 MB
__device__ float g_mt[DD * DD];    // M^T, B-packed for GEMM1   4 MB
__device__ float g_xlr[NN * DD];   // x_l, A-packed for GEMM1  16 MB
__device__ float g_xrr[NN * DD];   // x_r, B-packed for GEMM2  16 MB
__device__ float g_linl[NN];
__device__ float g_linr[NN];

__device__ __forceinline__ float tf32r(float x) {
    uint32_t y;
    asm("cvt.rna.tf32.f32 %0, %1;" : "=r"(y) : "f"(x));
    return __uint_as_float(y);
}
__device__ __forceinline__ uint32_t smaddr(const void* p) {
    uint64_t t;
    asm("cvta.to.shared.u64 %0, %1;" : "=l"(t) : "l"(p));
    return (uint32_t)t;
}
__device__ __forceinline__ void mbar_wait(uint32_t mbar, uint32_t parity) {
    asm volatile(
        "{\n\t.reg .pred P;\n\t"
        "WL_%=:\n\t"
        "mbarrier.try_wait.parity.acquire.cta.shared::cta.b64 P, [%0], %1, 0x989680;\n\t"
        "@P bra.uni WD_%=;\n\t"
        "bra.uni WL_%=;\n\t"
        "WD_%=:\n\t}"
        :: "r"(mbar), "r"(parity) : "memory");
}
__device__ __forceinline__ void bulk_cp(uint32_t dst, const void* src,
                                        uint32_t bytes, uint32_t mbar) {
    asm volatile(
        "cp.async.bulk.shared::cluster.global.mbarrier::complete_tx::bytes "
        "[%0], [%1], %2, [%3];"
        :: "r"(dst), "l"(src), "r"(bytes), "r"(mbar) : "memory");
}

// fragment-packed index of element (row, k) inside a 128x32 tile.
__device__ __forceinline__ int apack_inner(int row, int k) {
    int wm = row >> 5, mm = (row >> 4) & 1, sub8 = (row >> 3) & 1, g = row & 7;
    int kstep = k >> 3, half = (k >> 2) & 1, q = k & 3;
    return (((((kstep * 4 + wm) * 2 + mm) * 8 + g) * 4 + q) << 2) + half * 2 + sub8;
}
__device__ __forceinline__ int bpack_inner(int row, int k) {
    int wn = row >> 6, np = (row >> 4) & 3, nlo = (row >> 3) & 1, g = row & 7;
    int kstep = k >> 3, half = (k >> 2) & 1, q = k & 3;
    return (((((kstep * 2 + wn) * 4 + np) * 8 + g) * 4 + q) << 2) + nlo * 2 + half;
}

// ---------------------------------------------------------------------------
// Vectorized B-pack of one (rowTile, kTile) unit for source x (row-major).
// Thread unit: row pair (row, row+8) x one kstep; 4 LDG.128 + 4 STG.128.
// ---------------------------------------------------------------------------
__device__ __forceinline__ void bpack_unit(
    const float* __restrict__ src, float* __restrict__ dst,
    int rowTile, int kTile, int t)
{
    int p  = t & 63;
    int ks = t >> 6;
    int g2 = p & 7;
    int row = ((p >> 3) << 4) + g2;
    size_t sb = (size_t)(rowTile * 128 + row) * DD + kTile * 32 + ks * 8;
    float4 u0 = *(const float4*)&src[sb];
    float4 u1 = *(const float4*)&src[sb + 4];
    float4 v0 = *(const float4*)&src[sb + 8 * DD];
    float4 v1 = *(const float4*)&src[sb + 8 * DD + 4];
    float a0[8] = {tf32r(u0.x), tf32r(u0.y), tf32r(u0.z), tf32r(u0.w),
                   tf32r(u1.x), tf32r(u1.y), tf32r(u1.z), tf32r(u1.w)};
    float a8[8] = {tf32r(v0.x), tf32r(v0.y), tf32r(v0.z), tf32r(v0.w),
                   tf32r(v1.x), tf32r(v1.y), tf32r(v1.z), tf32r(v1.w)};
    float* dTile = dst + ((size_t)rowTile * NKT + kTile) * TILE_F;
    int wn = row >> 6, np = (row >> 4) & 3;
    int base = ((((ks * 2 + wn) * 4 + np) * 8 + g2) * 4) * 4;
    #pragma unroll
    for (int q = 0; q < 4; q++)
        *(float4*)&dTile[base + q * 4] =
            make_float4(a0[q], a0[q + 4], a8[q], a8[q + 4]);
}

// lin-term warp-per-row unit (gw in [0, 2*NN)).
__device__ __forceinline__ void lin_unit(
    const float* __restrict__ xl, const float* __restrict__ xr,
    const float* __restrict__ wl, const float* __restrict__ bl,
    const float* __restrict__ wr, const float* __restrict__ br,
    int gw, int lane)
{
    int right = gw >= NN;
    int row = right ? gw - NN : gw;
    const float* x = right ? xr : xl;
    const float* w = right ? wr : wl;
    const float4* xv = (const float4*)(x + (size_t)row * DD);
    const float4* wv = (const float4*)w;
    float s = 0.f;
    #pragma unroll
    for (int i = 0; i < 8; i++) {
        float4 a = xv[lane + i * 32];
        float4 bv = wv[lane + i * 32];
        s += a.x * bv.x + a.y * bv.y + a.z * bv.z + a.w * bv.w;
    }
    #pragma unroll
    for (int o = 16; o; o >>= 1) s += __shfl_xor_sync(0xffffffffu, s, o);
    if (lane == 0) {
        if (right) g_linr[row] = s + br[0];
        else       g_linl[row] = s + bl[0];
    }
}

// ---------------------------------------------------------------------------
// Prep phase 1 (GEMM1 dependencies only):
//   blocks [0,1024)   : pack x_l -> g_xlr (A-packed, vectorized)
//   blocks [1024,1280): pack M^T -> g_mt  (B-packed, transposed)
// ---------------------------------------------------------------------------
__global__ __launch_bounds__(256) void prep1_kernel(
    const float* __restrict__ xl, const float* __restrict__ matrix)
{
    const int b = blockIdx.x;
    const int t = threadIdx.x;

    if (b < 1024) {
        int rowTile = b >> 5;
        int kTile   = b & 31;
        int p  = t & 63;
        int ks = t >> 6;
        int g2 = p & 7;
        int row = ((p >> 3) << 4) + g2;
        size_t sb = (size_t)(rowTile * 128 + row) * DD + kTile * 32 + ks * 8;
        float4 u0 = *(const float4*)&xl[sb];
        float4 u1 = *(const float4*)&xl[sb + 4];
        float4 v0 = *(const float4*)&xl[sb + 8 * DD];
        float4 v1 = *(const float4*)&xl[sb + 8 * DD + 4];
        float a0[8] = {tf32r(u0.x), tf32r(u0.y), tf32r(u0.z), tf32r(u0.w),
                       tf32r(u1.x), tf32r(u1.y), tf32r(u1.z), tf32r(u1.w)};
        float a8[8] = {tf32r(v0.x), tf32r(v0.y), tf32r(v0.z), tf32r(v0.w),
                       tf32r(v1.x), tf32r(v1.y), tf32r(v1.z), tf32r(v1.w)};
        float* dTile = g_xlr + ((size_t)rowTile * NKT + kTile) * TILE_F;
        int wm = row >> 5, mm = (row >> 4) & 1;
        int base = ((((ks * 4 + wm) * 2 + mm) * 8 + g2) * 4) * 4;
        #pragma unroll
        for (int q = 0; q < 4; q++)
            *(float4*)&dTile[base + q * 4] =
                make_float4(a0[q], a8[q], a0[q + 4], a8[q + 4]);
    } else {
        int bb = b - 1024;
        int nTile = bb >> 5;
        int kTile = bb & 31;
        int k    = t >> 3;
        int nOff = (t & 7) * 16;
        size_t srcBase = (size_t)(kTile * 32 + k) * DD + nTile * 128 + nOff;
        float* dTile = g_mt + ((size_t)nTile * NKT + kTile) * TILE_F;
        #pragma unroll
        for (int j = 0; j < 4; j++) {
            float4 v = *(const float4*)&matrix[srcBase + j * 4];
            int nl = nOff + j * 4;
            float vv[4] = {v.x, v.y, v.z, v.w};
            #pragma unroll
            for (int e = 0; e < 4; e++)
                dTile[bpack_inner(nl + e, k)] = tf32r(vv[e]);
        }
    }
}

// ---------------------------------------------------------------------------
// tf32 NT GEMM on fragment-packed operands (R10 configuration) with an
// optional fused prep-2 region: blocks >= gemm_blocks run xr-pack / lin and
// exit (their results are consumed only by the NEXT launch).
// 1D grid; GEMM tile = (b % gx, b / gx).
// ---------------------------------------------------------------------------
__global__ __launch_bounds__(256, 2) void gemm_tc(
    const float* __restrict__ Apk, const float* __restrict__ Bpk,
    float* __restrict__ out,
    const int* __restrict__ mask, const float* __restrict__ bias,
    int mode, int write_x_half, int gemm_blocks, int gx,
    const float* __restrict__ xl_raw, const float* __restrict__ xr_raw,
    const float* __restrict__ wl, const float* __restrict__ bl,
    const float* __restrict__ wr, const float* __restrict__ br)
{
    extern __shared__ __align__(128) float4 sm4[];
    __shared__ __align__(8) uint64_t s_full[NSTAGE];
    __shared__ __align__(8) uint64_t s_empty[NSTAGE];

    const int b = blockIdx.x;
    if (b >= gemm_blocks) {
        // fused prep-2: xr B-pack (1024 blocks) then lin (1024 blocks)
        int pb = b - gemm_blocks;
        if (pb < 1024) {
            bpack_unit(xr_raw, g_xrr, pb >> 5, pb & 31, threadIdx.x);
        } else {
            int gw = ((pb - 1024) * 256 + threadIdx.x) >> 5;
            lin_unit(xl_raw, xr_raw, wl, bl, wr, br, gw, threadIdx.x & 31);
        }
        return;
    }

    const int tid  = threadIdx.x;
    const int lane = tid & 31;
    const int wid  = tid >> 5;
    const int wm   = wid >> 1;
    const int wn   = wid & 1;
    const int g    = lane >> 2;
    const int q    = lane & 3;
    const int bx   = b % gx;
    const int by   = b / gx;

    const uint32_t smB    = smaddr(sm4);
    const uint32_t fullB  = smaddr(&s_full[0]);
    const uint32_t emptyB = smaddr(&s_empty[0]);

    if (tid == 0) {
        #pragma unroll
        for (int s = 0; s < NSTAGE; s++) {
            asm volatile("mbarrier.init.shared.b64 [%0], 1;"
                         :: "r"(fullB + 8u * s) : "memory");
            asm volatile("mbarrier.init.shared.b64 [%0], 8;"
                         :: "r"(emptyB + 8u * s) : "memory");
        }
    }
    __syncthreads();

    const char* Ag = (const char*)Apk + (size_t)by * NKT * TILE_B;
    const char* Bg = (const char*)Bpk + (size_t)bx * NKT * TILE_B;

    auto issue = [&](int u) {
        int s2 = u % NSTAGE;
        uint32_t fb = fullB + 8u * s2;
        asm volatile("mbarrier.arrive.expect_tx.shared.b64 _, [%0], %1;"
                     :: "r"(fb), "r"((uint32_t)STAGE_B) : "memory");
        uint32_t d = smB + (uint32_t)s2 * STAGE_B;
        bulk_cp(d,          Ag + (size_t)u * TILE_B, TILE_B, fb);
        bulk_cp(d + TILE_B, Bg + (size_t)u * TILE_B, TILE_B, fb);
    };

    if (tid == 0) { issue(0); issue(1); }

    float c[2][8][4];
    #pragma unroll
    for (int mm = 0; mm < 2; mm++)
        #pragma unroll
        for (int nn = 0; nn < 8; nn++)
            #pragma unroll
            for (int r = 0; r < 4; r++) c[mm][nn][r] = 0.f;

    for (int t = 0; t < NKT; t++) {
        int s = t % NSTAGE;
        if (tid == 0 && t + 2 < NKT) {
            int u = t + 2;
            if (u >= NSTAGE)
                mbar_wait(emptyB + 8u * (u % NSTAGE), (u / NSTAGE - 1) & 1);
            issue(u);
        }
        mbar_wait(fullB + 8u * s, (t / NSTAGE) & 1);

        const float4* Af = sm4 + s * (STAGE_B / 16);
        const float4* Bf = Af + (TILE_B / 16);

        #pragma unroll
        for (int ks = 0; ks < 4; ks++) {
            float4 b4[4];
            #pragma unroll
            for (int np = 0; np < 4; np++)
                b4[np] = Bf[((ks * 2 + wn) * 4 + np) * 32 + lane];
            float4 a0 = Af[((ks * 4 + wm) * 2 + 0) * 32 + lane];
            float4 a1 = Af[((ks * 4 + wm) * 2 + 1) * 32 + lane];

            #pragma unroll
            for (int np = 0; np < 4; np++) {
                #pragma unroll
                for (int o = 0; o < 2; o++) {
                    int nn = np * 2 + o;
                    float bb0 = o ? b4[np].z : b4[np].x;
                    float bb1 = o ? b4[np].w : b4[np].y;
                    asm volatile(
                        "mma.sync.aligned.m16n8k8.row.col.f32.tf32.tf32.f32 "
                        "{%0,%1,%2,%3}, {%4,%5,%6,%7}, {%8,%9}, {%0,%1,%2,%3};"
                        : "+f"(c[0][nn][0]), "+f"(c[0][nn][1]),
                          "+f"(c[0][nn][2]), "+f"(c[0][nn][3])
                        : "r"(__float_as_uint(a0.x)), "r"(__float_as_uint(a0.y)),
                          "r"(__float_as_uint(a0.z)), "r"(__float_as_uint(a0.w)),
                          "r"(__float_as_uint(bb0)), "r"(__float_as_uint(bb1)));
                    asm volatile(
                        "mma.sync.aligned.m16n8k8.row.col.f32.tf32.tf32.f32 "
                        "{%0,%1,%2,%3}, {%4,%5,%6,%7}, {%8,%9}, {%0,%1,%2,%3};"
                        : "+f"(c[1][nn][0]), "+f"(c[1][nn][1]),
                          "+f"(c[1][nn][2]), "+f"(c[1][nn][3])
                        : "r"(__float_as_uint(a1.x)), "r"(__float_as_uint(a1.y)),
                          "r"(__float_as_uint(a1.z)), "r"(__float_as_uint(a1.w)),
                          "r"(__float_as_uint(bb0)), "r"(__float_as_uint(bb1)));
                }
            }
        }
        if (lane == 0)
            asm volatile("mbarrier.arrive.shared.b64 _, [%0];"
                         :: "r"(emptyB + 8u * s) : "memory");
    }

    if (mode == 0) {
        // store A-packed tf32 for GEMM2
        #pragma unroll
        for (int mm = 0; mm < 2; mm++) {
            #pragma unroll
            for (int nn = 0; nn < 8; nn++) {
                int colL = wn * 64 + nn * 8 + q * 2;
                int rowL = wm * 32 + mm * 16 + g;
                size_t tb = ((size_t)by * NKT + bx * 4 + (colL >> 5)) * TILE_F;
                int kl = colL & 31;
                out[tb + apack_inner(rowL,     kl)]     = tf32r(c[mm][nn][0]);
                out[tb + apack_inner(rowL,     kl + 1)] = tf32r(c[mm][nn][1]);
                out[tb + apack_inner(rowL + 8, kl)]     = tf32r(c[mm][nn][2]);
                out[tb + apack_inner(rowL + 8, kl + 1)] = tf32r(c[mm][nn][3]);
            }
        }
    } else {
        const float b0v = bias[0];
        const size_t xoff = (size_t)NN * NN;
        const int rowBase = by * BM;
        const int colBase = bx * BN;
        #pragma unroll
        for (int mm = 0; mm < 2; mm++) {
            int row0 = rowBase + wm * 32 + mm * 16 + g;
            int row1 = row0 + 8;
            float ll0 = g_linl[row0] + b0v;
            float ll1 = g_linl[row1] + b0v;
            #pragma unroll
            for (int nn = 0; nn < 8; nn++) {
                int col = colBase + wn * 64 + nn * 8 + q * 2;
                float lr0 = g_linr[col];
                float lr1 = g_linr[col + 1];
                float v00 = c[mm][nn][0] + ll0 + lr0; v00 = v00 > 0.f ? v00 : 0.f;
                float v01 = c[mm][nn][1] + ll0 + lr1; v01 = v01 > 0.f ? v01 : 0.f;
                float v10 = c[mm][nn][2] + ll1 + lr0; v10 = v10 > 0.f ? v10 : 0.f;
                float v11 = c[mm][nn][3] + ll1 + lr1; v11 = v11 > 0.f ? v11 : 0.f;
                size_t b0i = (size_t)row0 * NN + col;
                size_t b1i = (size_t)row1 * NN + col;
                if (write_x_half) {
                    *(float2*)&out[xoff + b0i] = make_float2(v00, v01);
                    *(float2*)&out[xoff + b1i] = make_float2(v10, v11);
                }
                int2 m0 = *(const int2*)&mask[b0i];
                int2 m1 = *(const int2*)&mask[b1i];
                *(float2*)&out[b0i] = make_float2(m0.x ? v00 : 0.f, m0.y ? v01 : 0.f);
                *(float2*)&out[b1i] = make_float2(m1.x ? v10 : 0.f, m1.y ? v11 : 0.f);
            }
        }
    }
}

// ---------------------------------------------------------------------------
extern "C" void kernel_launch(void* const* d_in, const int* in_sizes, int n_in,
                              void* d_out, int out_size)
{
    const float* xl     = (const float*)d_in[0];
    const float* xr     = (const float*)d_in[1];
    const int*   mask   = (const int*)d_in[2];
    const float* matrix = (const float*)d_in[3];
    const float* bias   = (const float*)d_in[4];
    const float* wl     = (const float*)d_in[5];
    const float* bl     = (const float*)d_in[6];
    const float* wr     = (const float*)d_in[7];
    const float* br     = (const float*)d_in[8];
    float* out = (float*)d_out;

    int write_x_half = (out_size >= 2 * NN * NN) ? 1 : 0;

    cudaFuncSetAttribute(gemm_tc,
                         cudaFuncAttributeMaxDynamicSharedMemorySize, GEMM_SMEM);

    float *xm, *mt, *xlr, *xrr;
    cudaGetSymbolAddress((void**)&xm, g_xm);
    cudaGetSymbolAddress((void**)&mt, g_mt);
    cudaGetSymbolAddress((void**)&xlr, g_xlr);
    cudaGetSymbolAddress((void**)&xrr, g_xrr);

    // 1) prep phase 1: GEMM1 dependencies only (xl pack + M^T pack)
    prep1_kernel<<<1280, 256>>>(xl, matrix);

    // 2) GEMM1 (256 tiles) + fused prep-2 (xr pack: 1024 blocks, lin: 1024)
    gemm_tc<<<256 + 2048, 256, GEMM_SMEM>>>(
        xlr, mt, xm, nullptr, nullptr, 0, 0,
        /*gemm_blocks=*/256, /*gx=*/DD / BN,
        xl, xr, wl, bl, wr, br);

    // 3) GEMM2: S = XM @ tf32(x_r)^T + epilogue (1024 tiles, 1D grid)
    gemm_tc<<<(NN / BM) * (NN / BN), 256, GEMM_SMEM>>>(
        xm, xrr, out, mask, bias, 1, write_x_half,
        /*gemm_blocks=*/1 << 30, /*gx=*/NN / BN,
        nullptr, nullptr, nullptr, nullptr, nullptr, nullptr);
}